// round 1
// baseline (speedup 1.0000x reference)
#include <cuda_runtime.h>

// Problem constants
#define TT   32768
#define DD   256
#define HH   256
#define KV   16
#define CH   128          // scan chunk length
#define NC   (TT/CH)      // 256 chunks
#define NBLK 2

// ---------------- device scratch (no allocations allowed) ----------------
__device__ float g_k[TT*KV];
__device__ float g_q[TT*KV];
__device__ float g_v[TT*KV];
__device__ float g_Sagg[NC*256];
__device__ float g_Zagg[NC];
__device__ int   g_pagg[NC];
__device__ float g_Spre[NC*256];
__device__ float g_Zpre[NC];
__device__ float g_h1[TT*HH];
__device__ float g_h2[TT*HH];
__device__ float g_ypre[TT*HH];
__device__ float g_x1[TT*HH];
__device__ int   g_startmode;   // 0=u8 bool, 1=int32, 2=float32

__device__ __forceinline__ float phi_fn(float t) {
    // 1 + elu(t) ; elu alpha=1 -> t>0 ? 1+t : exp(t)
    return (t > 0.f) ? (1.f + t) : __expf(t);
}

__device__ __forceinline__ int read_start(const void* p, int t, int mode) {
    if (mode == 0) return ((const unsigned char*)p)[t] != 0;
    if (mode == 1) return ((const int*)p)[t] != 0;
    return ((const float*)p)[t] != 0.f;
}

// ---------------- start-dtype classifier ----------------
__global__ void detect_kernel(const unsigned char* __restrict__ p) {
    __shared__ int cnt1, cnt3f;
    if (threadIdx.x == 0) { cnt1 = 0; cnt3f = 0; }
    __syncthreads();
    int l1 = 0, l3 = 0;
    for (int idx = threadIdx.x; idx < 4096; idx += 256) {
        unsigned char b = p[idx];
        if ((idx & 3) != 0 && b != 0) l1++;
        if ((idx & 3) == 3 && b == 0x3F) l3++;   // 1.0f high byte
    }
    atomicAdd(&cnt1, l1); atomicAdd(&cnt3f, l3);
    __syncthreads();
    if (threadIdx.x == 0) g_startmode = (cnt3f > 0) ? 2 : ((cnt1 > 0) ? 0 : 1);
}

// ---------------- k,q,v projections ----------------
// CTA: 32 rows. smem: weights transposed [c][48], x tile [32][260 padded].
__global__ void kqv_kernel(const float* __restrict__ xext, int use_x1,
                           const float* __restrict__ Wk, const float* __restrict__ Wq,
                           const float* __restrict__ Wv, const float* __restrict__ bv)
{
    extern __shared__ float sm[];
    float* wt = sm;                 // 256*48
    float* xs = sm + 48*256;        // 32*260
    const float* x = use_x1 ? g_x1 : xext;
    int tid = threadIdx.x;
    int base = blockIdx.x * 32;

    for (int idx = tid; idx < 48*256; idx += 256) {
        int o = idx >> 8, c = idx & 255;
        float w;
        if (o < 16)      w = Wk[o*256 + c];
        else if (o < 32) w = Wq[(o-16)*256 + c];
        else             w = Wv[(o-32)*256 + c];
        wt[c*48 + o] = w;
    }
    {
        const float4* xg = (const float4*)(x + (size_t)base * 256);
        for (int idx = tid; idx < 32*64; idx += 256) {
            int r = idx >> 6, c4 = idx & 63;
            ((float4*)(xs + r*260))[c4] = xg[idx];
        }
    }
    __syncthreads();

    int r = tid & 31;       // row within tile
    int g = tid >> 5;       // output group 0..7 (6 outputs each)
    float acc[6] = {0,0,0,0,0,0};
    const float* xr = xs + r*260;
    #pragma unroll 8
    for (int c = 0; c < 256; c++) {
        float xv = xr[c];
        const float* wr = wt + c*48 + g*6;
        #pragma unroll
        for (int m = 0; m < 6; m++) acc[m] += xv * wr[m];
    }
    int t = base + r;
    #pragma unroll
    for (int m = 0; m < 6; m++) {
        int o = g*6 + m;
        if (o < 16)       g_k[t*16 + o]      = phi_fn(acc[m]);
        else if (o < 32)  g_q[t*16 + (o-16)] = phi_fn(acc[m]);
        else              g_v[t*16 + (o-32)] = acc[m] + bv[o-32];
    }
}

// ---------------- pass 1: chunk aggregates ----------------
__global__ void agg_kernel(const void* __restrict__ startp)
{
    __shared__ float ks[CH*16], vs[CH*16], ksums[CH];
    __shared__ int stb[CH];
    int tid = threadIdx.x;
    int c = blockIdx.x;
    int tb = c * CH;
    int mode = g_startmode;
    for (int idx = tid; idx < CH*16; idx += 256) {
        ks[idx] = g_k[tb*16 + idx];
        vs[idx] = g_v[tb*16 + idx];
    }
    for (int idx = tid; idx < CH; idx += 256)
        stb[idx] = read_start(startp, tb + idx, mode);
    __syncthreads();
    for (int t = tid; t < CH; t += 256) {
        float s = 0.f;
        #pragma unroll
        for (int i = 0; i < 16; i++) s += ks[t*16 + i];
        ksums[t] = s;
    }
    __syncthreads();

    int i = tid & 15, j = tid >> 4;
    float S = 0.f, Zs = 0.f; int p = 0;
    for (int t = 0; t < CH; t++) {
        if (stb[t]) { S = 0.f; Zs = 0.f; p = 1; }
        S  += ks[t*16 + i] * vs[t*16 + j];
        Zs += ksums[t];
    }
    g_Sagg[c*256 + tid] = S;
    if (tid == 0) { g_Zagg[c] = Zs; g_pagg[c] = p; }
}

// ---------------- pass 2: chunk-prefix scan (1 CTA) ----------------
__global__ void prefix_kernel(const float* __restrict__ s0, const float* __restrict__ z0)
{
    int tid = threadIdx.x;
    int i = tid & 15, j = tid >> 4;
    float S = s0[i*16 + j];
    float Zs = 0.f;
    #pragma unroll
    for (int l = 0; l < 16; l++) Zs += z0[l];
    for (int c = 0; c < NC; c++) {
        g_Spre[c*256 + tid] = S;
        if (tid == 0) g_Zpre[c] = Zs;
        int p = g_pagg[c];
        float sa = g_Sagg[c*256 + tid];
        float za = g_Zagg[c];
        if (p) { S = 0.f; Zs = 0.f; }
        S += sa; Zs += za;
    }
}

// ---------------- pass 3: replay + attention output + MLP layer 1 ----------------
__global__ void apply_kernel(const void* __restrict__ startp,
                             const float* __restrict__ Wm1, const float* __restrict__ bm1)
{
    __shared__ float ks[CH*16], qs[CH*16], vs[CH*16], ksums[CH], qsums[CH];
    __shared__ int stb[CH];
    __shared__ float outb[2][16];
    int tid = threadIdx.x;
    int c = blockIdx.x;
    int tb = c * CH;
    int mode = g_startmode;
    for (int idx = tid; idx < CH*16; idx += 256) {
        ks[idx] = g_k[tb*16 + idx];
        qs[idx] = g_q[tb*16 + idx];
        vs[idx] = g_v[tb*16 + idx];
    }
    for (int idx = tid; idx < CH; idx += 256)
        stb[idx] = read_start(startp, tb + idx, mode);
    __syncthreads();
    for (int t = tid; t < CH; t += 256) {
        float sk = 0.f, sq = 0.f;
        #pragma unroll
        for (int i = 0; i < 16; i++) { sk += ks[t*16+i]; sq += qs[t*16+i]; }
        ksums[t] = sk; qsums[t] = sq;
    }
    float wm1r[16];
    #pragma unroll
    for (int l = 0; l < 16; l++) wm1r[l] = Wm1[tid*16 + l];
    float b1 = bm1[tid];
    float S  = g_Spre[c*256 + tid];
    float Zs = g_Zpre[c];
    __syncthreads();

    int i = tid & 15, j = tid >> 4;
    for (int t = 0; t < CH; t++) {
        if (stb[t]) { S = 0.f; Zs = 0.f; }
        S  += ks[t*16 + i] * vs[t*16 + j];
        Zs += ksums[t];
        float pv = S * qs[t*16 + i];
        pv += __shfl_down_sync(0xffffffffu, pv, 8, 16);
        pv += __shfl_down_sync(0xffffffffu, pv, 4, 16);
        pv += __shfl_down_sync(0xffffffffu, pv, 2, 16);
        pv += __shfl_down_sync(0xffffffffu, pv, 1, 16);
        if (i == 0) {
            float denom = fmaxf(Zs * qsums[t], 1e-6f);
            outb[t & 1][j] = pv / denom;
        }
        __syncthreads();
        const float* ob = outb[t & 1];
        float h = b1;
        #pragma unroll
        for (int l = 0; l < 16; l++) h += wm1r[l] * ob[l];
        h = (h > 0.f) ? h : 0.01f * h;
        g_h1[(size_t)(tb + t) * 256 + tid] = h;
    }
}

// ---------------- big GEMM: C = act(A @ W^T + bias) ----------------
// variant 0: g_h2  = leaky(g_h1 @ W1^T + b1),            Ktot=256
// variant 1: g_ypre= g_h2 @ W1^T + A2ext @ W2^T + b1+b2, Ktot=512 (A2 external)
// variant 2: same as 1 but A2 = g_x1
__global__ void __launch_bounds__(256, 2)
gemm_kernel(const float* __restrict__ A2ext,
            const float* __restrict__ W1, const float* __restrict__ W2,
            const float* __restrict__ b1p, const float* __restrict__ b2p,
            int variant)
{
    __shared__ float As[16][132];
    __shared__ float Bs[16][132];
    const float* A1 = (variant == 0) ? g_h1 : g_h2;
    const float* A2 = (variant == 2) ? g_x1 : A2ext;
    float* C        = (variant == 0) ? g_h2 : g_ypre;
    int Ktot        = (variant == 0) ? 256 : 512;
    int act         = (variant == 0) ? 1 : 0;

    int tid = threadIdx.x;
    int rowbase = blockIdx.y * 128;
    int colbase = blockIdx.x * 128;
    int tx = tid & 15, ty = tid >> 4;

    float acc[8][8];
    #pragma unroll
    for (int u = 0; u < 8; u++)
        #pragma unroll
        for (int v = 0; v < 8; v++) acc[u][v] = 0.f;

    for (int kb = 0; kb < Ktot; kb += 16) {
        const float* Asrc; const float* Wsrc; int koff;
        if (kb < 256) { Asrc = A1; Wsrc = W1; koff = kb; }
        else          { Asrc = A2; Wsrc = W2; koff = kb - 256; }
        #pragma unroll
        for (int s = 0; s < 2; s++) {
            int id = tid + s*256;
            int m  = id >> 2;
            int kq = (id & 3) * 4;
            float4 av = *(const float4*)(Asrc + (size_t)(rowbase + m)*256 + koff + kq);
            As[kq+0][m] = av.x; As[kq+1][m] = av.y; As[kq+2][m] = av.z; As[kq+3][m] = av.w;
            float4 wv = *(const float4*)(Wsrc + (size_t)(colbase + m)*256 + koff + kq);
            Bs[kq+0][m] = wv.x; Bs[kq+1][m] = wv.y; Bs[kq+2][m] = wv.z; Bs[kq+3][m] = wv.w;
        }
        __syncthreads();
        #pragma unroll
        for (int kc = 0; kc < 16; kc++) {
            float a[8], bb[8];
            *(float4*)(a)    = *(const float4*)&As[kc][ty*8];
            *(float4*)(a+4)  = *(const float4*)&As[kc][ty*8+4];
            *(float4*)(bb)   = *(const float4*)&Bs[kc][tx*8];
            *(float4*)(bb+4) = *(const float4*)&Bs[kc][tx*8+4];
            #pragma unroll
            for (int u = 0; u < 8; u++)
                #pragma unroll
                for (int v = 0; v < 8; v++) acc[u][v] += a[u] * bb[v];
        }
        __syncthreads();
    }

    float bias[8];
    #pragma unroll
    for (int v = 0; v < 8; v++) {
        int col = colbase + tx*8 + v;
        bias[v] = b1p[col] + ((variant != 0) ? b2p[col] : 0.f);
    }
    #pragma unroll
    for (int u = 0; u < 8; u++) {
        int row = rowbase + ty*8 + u;
        #pragma unroll
        for (int v = 0; v < 8; v++) {
            float val = acc[u][v] + bias[v];
            if (act) val = (val > 0.f) ? val : 0.01f * val;
            C[(size_t)row * 256 + colbase + tx*8 + v] = val;
        }
    }
}

// ---------------- LayerNorm + residual ----------------
// mode 0: g_x1 = xext + LN(g_ypre)   (block 0)
// mode 1: outext = LN(g_ypre)        (block 1, final output)
__global__ void ln_kernel(const float* __restrict__ xext, float* __restrict__ outext,
                          const float* __restrict__ lw, const float* __restrict__ lb, int mode)
{
    int tid = threadIdx.x;
    int lane = tid & 31, w = tid >> 5;
    int row = blockIdx.x * 8 + w;
    const float* yp = g_ypre + (size_t)row * 256;
    float vals[8];
    float s = 0.f;
    #pragma unroll
    for (int u = 0; u < 8; u++) { vals[u] = yp[lane + u*32]; s += vals[u]; }
    #pragma unroll
    for (int d = 16; d >= 1; d >>= 1) s += __shfl_xor_sync(0xffffffffu, s, d);
    float mean = s * (1.f / 256.f);
    float v2 = 0.f;
    #pragma unroll
    for (int u = 0; u < 8; u++) { float d = vals[u] - mean; v2 += d * d; }
    #pragma unroll
    for (int d = 16; d >= 1; d >>= 1) v2 += __shfl_xor_sync(0xffffffffu, v2, d);
    float rstd = rsqrtf(v2 * (1.f / 256.f) + 1e-5f);

    if (mode == 0) {
        float* o = g_x1 + (size_t)row * 256;
        const float* xr = xext + (size_t)row * 256;
        #pragma unroll
        for (int u = 0; u < 8; u++) {
            int cl = lane + u*32;
            o[cl] = xr[cl] + (vals[u] - mean) * rstd * lw[cl] + lb[cl];
        }
    } else {
        float* o = outext + (size_t)row * 256;
        #pragma unroll
        for (int u = 0; u < 8; u++) {
            int cl = lane + u*32;
            o[cl] = (vals[u] - mean) * rstd * lw[cl] + lb[cl];
        }
    }
}

// ---------------- launch ----------------
extern "C" void kernel_launch(void* const* d_in, const int* in_sizes, int n_in,
                              void* d_out, int out_size)
{
    const float* x     = (const float*)d_in[0];
    const void*  start = d_in[1];
    const float* s0    = (const float*)d_in[2];
    const float* z0    = (const float*)d_in[3];
    const float* Wk    = (const float*)d_in[4];
    const float* Wq    = (const float*)d_in[5];
    const float* Wv    = (const float*)d_in[6];
    const float* bv    = (const float*)d_in[7];
    const float* Wskip = (const float*)d_in[8];
    const float* bskip = (const float*)d_in[9];
    const float* Wm1   = (const float*)d_in[10];
    const float* bm1   = (const float*)d_in[11];
    const float* Wm2   = (const float*)d_in[12];
    const float* bm2   = (const float*)d_in[13];
    const float* Wm3   = (const float*)d_in[14];
    const float* bm3   = (const float*)d_in[15];
    const float* lnw   = (const float*)d_in[16];
    const float* lnb   = (const float*)d_in[17];
    float* out = (float*)d_out;

    const int kqv_smem = (48*256 + 32*260) * 4;   // 82432 bytes
    cudaFuncSetAttribute(kqv_kernel, cudaFuncAttributeMaxDynamicSharedMemorySize, kqv_smem);

    detect_kernel<<<1, 256>>>((const unsigned char*)start);

    for (int b = 0; b < NBLK; b++) {
        kqv_kernel<<<TT/32, 256, kqv_smem>>>(x, b,
            Wk + b*16*256, Wq + b*16*256, Wv + b*16*256, bv + b*16);
        agg_kernel<<<NC, 256>>>(start);
        prefix_kernel<<<1, 256>>>(s0 + b*256, z0 + b*16);
        apply_kernel<<<NC, 256>>>(start, Wm1 + b*256*16, bm1 + b*256);
        gemm_kernel<<<dim3(2, TT/128), 256>>>(nullptr,
            Wm2 + b*256*256, nullptr, bm2 + b*256, nullptr, 0);
        gemm_kernel<<<dim3(2, TT/128), 256>>>(x,
            Wm3 + b*256*256, Wskip + b*256*256, bm3 + b*256, bskip + b*256,
            (b == 0) ? 1 : 2);
        ln_kernel<<<TT/8, 256>>>(x, out, lnw + b*256, lnb + b*256, (b == 0) ? 0 : 1);
    }
}

// round 2
// speedup vs baseline: 1.2956x; 1.2956x over previous
#include <cuda_runtime.h>

typedef unsigned long long u64;

// Problem constants
#define TT   32768
#define DD   256
#define HH   256
#define KV   16
#define CH   128          // scan chunk length
#define NC   (TT/CH)      // 256 chunks
#define NBLK 2

// ---------------- device scratch (no allocations allowed) ----------------
__device__ float g_k[TT*KV];
__device__ float g_q[TT*KV];
__device__ float g_v[TT*KV];
__device__ float g_Sagg[NC*256];
__device__ float g_Zagg[NC];
__device__ int   g_pagg[NC];
__device__ float g_Spre[NC*256];
__device__ float g_Zpre[NC];
__device__ float g_h1[TT*HH];
__device__ float g_h2[TT*HH];
__device__ float g_ypre[TT*HH];
__device__ float g_x1[TT*HH];
__device__ int   g_startmode;   // 0=u8 bool, 1=int32, 2=float32

// ---------------- f32x2 packed helpers (sm_103a FFMA2) ----------------
__device__ __forceinline__ u64 dup2(float x) {
    u64 r;
    asm("mov.b64 %0, {%1, %1};" : "=l"(r) : "r"(__float_as_uint(x)));
    return r;
}
__device__ __forceinline__ u64 fma2(u64 a, u64 b, u64 c) {
    u64 d;
    asm("fma.rn.f32x2 %0, %1, %2, %3;" : "=l"(d) : "l"(a), "l"(b), "l"(c));
    return d;
}
__device__ __forceinline__ void unpack2(u64 v, float& lo, float& hi) {
    unsigned int a, b;
    asm("mov.b64 {%0, %1}, %2;" : "=r"(a), "=r"(b) : "l"(v));
    lo = __uint_as_float(a); hi = __uint_as_float(b);
}

__device__ __forceinline__ float phi_fn(float t) {
    // 1 + elu(t) ; elu alpha=1 -> t>0 ? 1+t : exp(t)
    return (t > 0.f) ? (1.f + t) : __expf(t);
}

__device__ __forceinline__ int read_start(const void* p, int t, int mode) {
    if (mode == 0) return ((const unsigned char*)p)[t] != 0;
    if (mode == 1) return ((const int*)p)[t] != 0;
    return ((const float*)p)[t] != 0.f;
}

// ---------------- start-dtype classifier ----------------
__global__ void detect_kernel(const unsigned char* __restrict__ p) {
    __shared__ int cnt1, cnt3f;
    if (threadIdx.x == 0) { cnt1 = 0; cnt3f = 0; }
    __syncthreads();
    int l1 = 0, l3 = 0;
    for (int idx = threadIdx.x; idx < 4096; idx += 256) {
        unsigned char b = p[idx];
        if ((idx & 3) != 0 && b != 0) l1++;
        if ((idx & 3) == 3 && b == 0x3F) l3++;   // 1.0f high byte
    }
    atomicAdd(&cnt1, l1); atomicAdd(&cnt3f, l3);
    __syncthreads();
    if (threadIdx.x == 0) g_startmode = (cnt3f > 0) ? 2 : ((cnt1 > 0) ? 0 : 1);
}

// ---------------- k,q,v projections ----------------
// CTA: 128 rows. smem: weights [c][64] (8 groups of 6 outputs, group stride 8),
// x tile [128][257] (conflict-free stride). f32x2 accumulation.
// Thread (r0 = tid&31, g = tid>>5): rows r0+{0,32,64,96}, outputs g*6..g*6+5.
#define KQV_ROWS 128
__global__ void kqv_kernel(const float* __restrict__ xext, int use_x1,
                           const float* __restrict__ Wk, const float* __restrict__ Wq,
                           const float* __restrict__ Wv, const float* __restrict__ bv)
{
    extern __shared__ float sm[];
    float* wt = sm;                  // 256*64
    float* xs = sm + 256*64;         // 128*257
    const float* x = use_x1 ? g_x1 : xext;
    int tid = threadIdx.x;
    int base = blockIdx.x * KQV_ROWS;

    // stage weights: output o -> group g=o/6, slot m=o%6 at column g*8+m
    for (int idx = tid; idx < 48*256; idx += 256) {
        int o = idx >> 8, c = idx & 255;
        float w;
        if (o < 16)      w = Wk[o*256 + c];
        else if (o < 32) w = Wq[(o-16)*256 + c];
        else             w = Wv[(o-32)*256 + c];
        int gg = o / 6, mm = o - gg*6;
        wt[c*64 + gg*8 + mm] = w;
    }
    // stage x tile (scalar stores into stride-257 rows)
    {
        const float* xg = x + (size_t)base * 256;
        for (int idx = tid; idx < KQV_ROWS*64; idx += 256) {
            int r = idx >> 6, c4 = (idx & 63) * 4;
            float4 v = *(const float4*)(xg + r*256 + c4);
            float* d = xs + r*257 + c4;
            d[0] = v.x; d[1] = v.y; d[2] = v.z; d[3] = v.w;
        }
    }
    __syncthreads();

    int r0 = tid & 31;
    int g  = tid >> 5;
    u64 acc[4][3];
    #pragma unroll
    for (int rr = 0; rr < 4; rr++)
        #pragma unroll
        for (int pi = 0; pi < 3; pi++) acc[rr][pi] = 0ull;

    const float* wbase = wt + g*8;
    #pragma unroll 2
    for (int c = 0; c < 256; c++) {
        const float* wr = wbase + c*64;
        u64 w0 = *(const u64*)(wr + 0);
        u64 w1 = *(const u64*)(wr + 2);
        u64 w2 = *(const u64*)(wr + 4);
        #pragma unroll
        for (int rr = 0; rr < 4; rr++) {
            float xv = xs[(r0 + rr*32)*257 + c];
            u64 xd = dup2(xv);
            acc[rr][0] = fma2(xd, w0, acc[rr][0]);
            acc[rr][1] = fma2(xd, w1, acc[rr][1]);
            acc[rr][2] = fma2(xd, w2, acc[rr][2]);
        }
    }

    #pragma unroll
    for (int rr = 0; rr < 4; rr++) {
        int t = base + r0 + rr*32;
        #pragma unroll
        for (int pi = 0; pi < 3; pi++) {
            float lo, hi;
            unpack2(acc[rr][pi], lo, hi);
            #pragma unroll
            for (int h = 0; h < 2; h++) {
                int o = g*6 + pi*2 + h;
                float val = h ? hi : lo;
                if (o < 16)       g_k[t*16 + o]      = phi_fn(val);
                else if (o < 32)  g_q[t*16 + (o-16)] = phi_fn(val);
                else              g_v[t*16 + (o-32)] = val + bv[o-32];
            }
        }
    }
}

// ---------------- pass 1: chunk aggregates ----------------
__global__ void agg_kernel(const void* __restrict__ startp)
{
    __shared__ float ks[CH*16], vs[CH*16], ksums[CH];
    __shared__ int stb[CH];
    int tid = threadIdx.x;
    int c = blockIdx.x;
    int tb = c * CH;
    int mode = g_startmode;
    for (int idx = tid; idx < CH*16; idx += 256) {
        ks[idx] = g_k[tb*16 + idx];
        vs[idx] = g_v[tb*16 + idx];
    }
    for (int idx = tid; idx < CH; idx += 256)
        stb[idx] = read_start(startp, tb + idx, mode);
    __syncthreads();
    for (int t = tid; t < CH; t += 256) {
        float s = 0.f;
        #pragma unroll
        for (int i = 0; i < 16; i++) s += ks[t*16 + i];
        ksums[t] = s;
    }
    __syncthreads();

    int i = tid & 15, j = tid >> 4;
    float S = 0.f, Zs = 0.f; int p = 0;
    for (int t = 0; t < CH; t++) {
        if (stb[t]) { S = 0.f; Zs = 0.f; p = 1; }
        S  += ks[t*16 + i] * vs[t*16 + j];
        Zs += ksums[t];
    }
    g_Sagg[c*256 + tid] = S;
    if (tid == 0) { g_Zagg[c] = Zs; g_pagg[c] = p; }
}

// ---------------- pass 2: chunk-prefix scan (1 CTA, software-pipelined) --------
#define PD 16   // prefetch depth
__global__ void prefix_kernel(const float* __restrict__ s0, const float* __restrict__ z0)
{
    int tid = threadIdx.x;
    int i = tid & 15, j = tid >> 4;
    float S = s0[i*16 + j];
    float Zs = 0.f;
    #pragma unroll
    for (int l = 0; l < 16; l++) Zs += z0[l];

    float sa[PD], za[PD]; int pp[PD];
    #pragma unroll
    for (int d = 0; d < PD; d++) {
        sa[d] = g_Sagg[d*256 + tid];
        za[d] = g_Zagg[d];
        pp[d] = g_pagg[d];
    }
    for (int c = 0; c < NC; c += PD) {
        #pragma unroll
        for (int d = 0; d < PD; d++) {
            g_Spre[(c+d)*256 + tid] = S;
            if (tid == 0) g_Zpre[c+d] = Zs;
            float s_ = sa[d], z_ = za[d];
            int   p_ = pp[d];
            int n = c + d + PD;
            if (n < NC) {
                sa[d] = g_Sagg[n*256 + tid];
                za[d] = g_Zagg[n];
                pp[d] = g_pagg[n];
            }
            if (p_) { S = 0.f; Zs = 0.f; }
            S += s_; Zs += z_;
        }
    }
}

// ---------------- pass 3: replay + attention output + MLP layer 1 ----------------
__global__ void apply_kernel(const void* __restrict__ startp,
                             const float* __restrict__ Wm1, const float* __restrict__ bm1)
{
    __shared__ float ks[CH*16], qs[CH*16], vs[CH*16], ksums[CH], qsums[CH];
    __shared__ int stb[CH];
    __shared__ float outb[2][16];
    int tid = threadIdx.x;
    int c = blockIdx.x;
    int tb = c * CH;
    int mode = g_startmode;
    for (int idx = tid; idx < CH*16; idx += 256) {
        ks[idx] = g_k[tb*16 + idx];
        qs[idx] = g_q[tb*16 + idx];
        vs[idx] = g_v[tb*16 + idx];
    }
    for (int idx = tid; idx < CH; idx += 256)
        stb[idx] = read_start(startp, tb + idx, mode);
    __syncthreads();
    for (int t = tid; t < CH; t += 256) {
        float sk = 0.f, sq = 0.f;
        #pragma unroll
        for (int i = 0; i < 16; i++) { sk += ks[t*16+i]; sq += qs[t*16+i]; }
        ksums[t] = sk; qsums[t] = sq;
    }
    float wm1r[16];
    #pragma unroll
    for (int l = 0; l < 16; l++) wm1r[l] = Wm1[tid*16 + l];
    float b1 = bm1[tid];
    float S  = g_Spre[c*256 + tid];
    float Zs = g_Zpre[c];
    __syncthreads();

    int i = tid & 15, j = tid >> 4;
    for (int t = 0; t < CH; t++) {
        if (stb[t]) { S = 0.f; Zs = 0.f; }
        S  += ks[t*16 + i] * vs[t*16 + j];
        Zs += ksums[t];
        float pv = S * qs[t*16 + i];
        pv += __shfl_down_sync(0xffffffffu, pv, 8, 16);
        pv += __shfl_down_sync(0xffffffffu, pv, 4, 16);
        pv += __shfl_down_sync(0xffffffffu, pv, 2, 16);
        pv += __shfl_down_sync(0xffffffffu, pv, 1, 16);
        if (i == 0) {
            float denom = fmaxf(Zs * qsums[t], 1e-6f);
            outb[t & 1][j] = pv / denom;
        }
        __syncthreads();
        const float* ob = outb[t & 1];
        float h = b1;
        #pragma unroll
        for (int l = 0; l < 16; l++) h += wm1r[l] * ob[l];
        h = (h > 0.f) ? h : 0.01f * h;
        g_h1[(size_t)(tb + t) * 256 + tid] = h;
    }
}

// ---------------- big GEMM: C = act(A @ W^T + bias), f32x2, double-buffered ----
// variant 0: g_h2  = leaky(g_h1 @ W1^T + b1),            Ktot=256
// variant 1: g_ypre= g_h2 @ W1^T + A2ext @ W2^T + b1+b2, Ktot=512 (A2 external)
// variant 2: same as 1 but A2 = g_x1
__global__ void __launch_bounds__(256, 2)
gemm_kernel(const float* __restrict__ A2ext,
            const float* __restrict__ W1, const float* __restrict__ W2,
            const float* __restrict__ b1p, const float* __restrict__ b2p,
            int variant)
{
    __shared__ float As[2][16][132];
    __shared__ float Bs[2][16][132];
    const float* A1 = (variant == 0) ? g_h1 : g_h2;
    const float* A2 = (variant == 2) ? g_x1 : A2ext;
    float* C        = (variant == 0) ? g_h2 : g_ypre;
    int nkb         = (variant == 0) ? 16 : 32;   // K blocks of 16
    int act         = (variant == 0) ? 1 : 0;

    int tid = threadIdx.x;
    int rowbase = blockIdx.y * 128;
    int colbase = blockIdx.x * 128;
    int tx = tid & 15, ty = tid >> 4;

    // staging indices (two 256-thread sweeps cover 128 rows x 16 k)
    int m0 = tid >> 2;              // 0..63
    int kq = (tid & 3) * 4;         // 0,4,8,12

    u64 acc[8][4];
    #pragma unroll
    for (int u = 0; u < 8; u++)
        #pragma unroll
        for (int v = 0; v < 4; v++) acc[u][v] = 0ull;

    float4 av0, av1, wv0, wv1;

    // prologue: load kb=0
    {
        const float* Asrc = A1; const float* Wsrc = W1; int koff = 0;
        av0 = *(const float4*)(Asrc + (size_t)(rowbase + m0)*256 + koff + kq);
        wv0 = *(const float4*)(Wsrc + (size_t)(colbase + m0)*256 + koff + kq);
        av1 = *(const float4*)(Asrc + (size_t)(rowbase + m0 + 64)*256 + koff + kq);
        wv1 = *(const float4*)(Wsrc + (size_t)(colbase + m0 + 64)*256 + koff + kq);
        As[0][kq+0][m0] = av0.x; As[0][kq+1][m0] = av0.y; As[0][kq+2][m0] = av0.z; As[0][kq+3][m0] = av0.w;
        Bs[0][kq+0][m0] = wv0.x; Bs[0][kq+1][m0] = wv0.y; Bs[0][kq+2][m0] = wv0.z; Bs[0][kq+3][m0] = wv0.w;
        As[0][kq+0][m0+64] = av1.x; As[0][kq+1][m0+64] = av1.y; As[0][kq+2][m0+64] = av1.z; As[0][kq+3][m0+64] = av1.w;
        Bs[0][kq+0][m0+64] = wv1.x; Bs[0][kq+1][m0+64] = wv1.y; Bs[0][kq+2][m0+64] = wv1.z; Bs[0][kq+3][m0+64] = wv1.w;
    }
    __syncthreads();

    for (int kbi = 0; kbi < nkb; kbi++) {
        int cur = kbi & 1;
        int nxt = cur ^ 1;
        // prefetch next kb into registers (latency hidden by compute)
        if (kbi + 1 < nkb) {
            int kb = (kbi + 1) * 16;
            const float* Asrc; const float* Wsrc; int koff;
            if (kb < 256) { Asrc = A1; Wsrc = W1; koff = kb; }
            else          { Asrc = A2; Wsrc = W2; koff = kb - 256; }
            av0 = *(const float4*)(Asrc + (size_t)(rowbase + m0)*256 + koff + kq);
            wv0 = *(const float4*)(Wsrc + (size_t)(colbase + m0)*256 + koff + kq);
            av1 = *(const float4*)(Asrc + (size_t)(rowbase + m0 + 64)*256 + koff + kq);
            wv1 = *(const float4*)(Wsrc + (size_t)(colbase + m0 + 64)*256 + koff + kq);
        }
        // compute on current buffer
        #pragma unroll
        for (int kc = 0; kc < 16; kc++) {
            float a[8];
            *(float4*)(a)    = *(const float4*)&As[cur][kc][ty*8];
            *(float4*)(a+4)  = *(const float4*)&As[cur][kc][ty*8+4];
            const u64* bsrc = (const u64*)&Bs[cur][kc][tx*8];
            u64 bp0 = bsrc[0], bp1 = bsrc[1], bp2 = bsrc[2], bp3 = bsrc[3];
            #pragma unroll
            for (int u = 0; u < 8; u++) {
                u64 ad = dup2(a[u]);
                acc[u][0] = fma2(ad, bp0, acc[u][0]);
                acc[u][1] = fma2(ad, bp1, acc[u][1]);
                acc[u][2] = fma2(ad, bp2, acc[u][2]);
                acc[u][3] = fma2(ad, bp3, acc[u][3]);
            }
        }
        // store prefetched regs into next buffer
        if (kbi + 1 < nkb) {
            As[nxt][kq+0][m0] = av0.x; As[nxt][kq+1][m0] = av0.y; As[nxt][kq+2][m0] = av0.z; As[nxt][kq+3][m0] = av0.w;
            Bs[nxt][kq+0][m0] = wv0.x; Bs[nxt][kq+1][m0] = wv0.y; Bs[nxt][kq+2][m0] = wv0.z; Bs[nxt][kq+3][m0] = wv0.w;
            As[nxt][kq+0][m0+64] = av1.x; As[nxt][kq+1][m0+64] = av1.y; As[nxt][kq+2][m0+64] = av1.z; As[nxt][kq+3][m0+64] = av1.w;
            Bs[nxt][kq+0][m0+64] = wv1.x; Bs[nxt][kq+1][m0+64] = wv1.y; Bs[nxt][kq+2][m0+64] = wv1.z; Bs[nxt][kq+3][m0+64] = wv1.w;
            __syncthreads();
        }
    }

    float bias[8];
    #pragma unroll
    for (int v = 0; v < 8; v++) {
        int col = colbase + tx*8 + v;
        bias[v] = b1p[col] + ((variant != 0) ? b2p[col] : 0.f);
    }
    #pragma unroll
    for (int u = 0; u < 8; u++) {
        int row = rowbase + ty*8 + u;
        float o[8];
        #pragma unroll
        for (int vp = 0; vp < 4; vp++) unpack2(acc[u][vp], o[vp*2], o[vp*2+1]);
        #pragma unroll
        for (int v = 0; v < 8; v++) {
            float val = o[v] + bias[v];
            if (act) val = (val > 0.f) ? val : 0.01f * val;
            o[v] = val;
        }
        float* cdst = C + (size_t)row * 256 + colbase + tx*8;
        *(float4*)(cdst)   = make_float4(o[0], o[1], o[2], o[3]);
        *(float4*)(cdst+4) = make_float4(o[4], o[5], o[6], o[7]);
    }
}

// ---------------- LayerNorm + residual ----------------
// mode 0: g_x1 = xext + LN(g_ypre)   (block 0)
// mode 1: outext = LN(g_ypre)        (block 1, final output)
__global__ void ln_kernel(const float* __restrict__ xext, float* __restrict__ outext,
                          const float* __restrict__ lw, const float* __restrict__ lb, int mode)
{
    int tid = threadIdx.x;
    int lane = tid & 31, w = tid >> 5;
    int row = blockIdx.x * 8 + w;
    const float* yp = g_ypre + (size_t)row * 256;
    float vals[8];
    float s = 0.f;
    #pragma unroll
    for (int u = 0; u < 8; u++) { vals[u] = yp[lane + u*32]; s += vals[u]; }
    #pragma unroll
    for (int d = 16; d >= 1; d >>= 1) s += __shfl_xor_sync(0xffffffffu, s, d);
    float mean = s * (1.f / 256.f);
    float v2 = 0.f;
    #pragma unroll
    for (int u = 0; u < 8; u++) { float d = vals[u] - mean; v2 += d * d; }
    #pragma unroll
    for (int d = 16; d >= 1; d >>= 1) v2 += __shfl_xor_sync(0xffffffffu, v2, d);
    float rstd = rsqrtf(v2 * (1.f / 256.f) + 1e-5f);

    if (mode == 0) {
        float* o = g_x1 + (size_t)row * 256;
        const float* xr = xext + (size_t)row * 256;
        #pragma unroll
        for (int u = 0; u < 8; u++) {
            int cl = lane + u*32;
            o[cl] = xr[cl] + (vals[u] - mean) * rstd * lw[cl] + lb[cl];
        }
    } else {
        float* o = outext + (size_t)row * 256;
        #pragma unroll
        for (int u = 0; u < 8; u++) {
            int cl = lane + u*32;
            o[cl] = (vals[u] - mean) * rstd * lw[cl] + lb[cl];
        }
    }
}

// ---------------- launch ----------------
extern "C" void kernel_launch(void* const* d_in, const int* in_sizes, int n_in,
                              void* d_out, int out_size)
{
    const float* x     = (const float*)d_in[0];
    const void*  start = d_in[1];
    const float* s0    = (const float*)d_in[2];
    const float* z0    = (const float*)d_in[3];
    const float* Wk    = (const float*)d_in[4];
    const float* Wq    = (const float*)d_in[5];
    const float* Wv    = (const float*)d_in[6];
    const float* bv    = (const float*)d_in[7];
    const float* Wskip = (const float*)d_in[8];
    const float* bskip = (const float*)d_in[9];
    const float* Wm1   = (const float*)d_in[10];
    const float* bm1   = (const float*)d_in[11];
    const float* Wm2   = (const float*)d_in[12];
    const float* bm2   = (const float*)d_in[13];
    const float* Wm3   = (const float*)d_in[14];
    const float* bm3   = (const float*)d_in[15];
    const float* lnw   = (const float*)d_in[16];
    const float* lnb   = (const float*)d_in[17];
    float* out = (float*)d_out;

    const int kqv_smem = (256*64 + KQV_ROWS*257) * 4;   // 197120 bytes
    cudaFuncSetAttribute(kqv_kernel, cudaFuncAttributeMaxDynamicSharedMemorySize, kqv_smem);

    detect_kernel<<<1, 256>>>((const unsigned char*)start);

    for (int b = 0; b < NBLK; b++) {
        kqv_kernel<<<TT/KQV_ROWS, 256, kqv_smem>>>(x, b,
            Wk + b*16*256, Wq + b*16*256, Wv + b*16*256, bv + b*16);
        agg_kernel<<<NC, 256>>>(start);
        prefix_kernel<<<1, 256>>>(s0 + b*256, z0 + b*16);
        apply_kernel<<<NC, 256>>>(start, Wm1 + b*256*16, bm1 + b*256);
        gemm_kernel<<<dim3(2, TT/128), 256>>>(nullptr,
            Wm2 + b*256*256, nullptr, bm2 + b*256, nullptr, 0);
        gemm_kernel<<<dim3(2, TT/128), 256>>>(x,
            Wm3 + b*256*256, Wskip + b*256*256, bm3 + b*256, bskip + b*256,
            (b == 0) ? 1 : 2);
        ln_kernel<<<TT/8, 256>>>(x, out, lnw + b*256, lnb + b*256, (b == 0) ? 0 : 1);
    }
}

// round 4
// speedup vs baseline: 2.0773x; 1.6033x over previous
#include <cuda_runtime.h>
#include <cstdint>

typedef unsigned long long u64;
typedef unsigned int u32;

// Problem constants
#define TT   32768
#define DD   256
#define HH   256
#define KV   16
#define CH   128          // scan chunk length
#define NC   (TT/CH)      // 256 chunks
#define NBLK 2

// ---------------- device scratch (no allocations allowed) ----------------
__device__ float g_k[TT*KV];
__device__ float g_q[TT*KV];
__device__ float g_v[TT*KV];
__device__ float g_Sagg[NC*256];
__device__ float g_Zagg[NC];
__device__ int   g_pagg[NC];
__device__ float g_Spre[NC*256];
__device__ float g_Zpre[NC];
__device__ float g_h1[TT*HH];
__device__ float g_h2[TT*HH];
__device__ float g_ypre[TT*HH];
__device__ float g_x1[TT*HH];
__device__ int   g_startmode;   // 0=u8 bool, 1=int32, 2=float32

// ---------------- f32x2 packed helpers (sm_103a FFMA2) ----------------
__device__ __forceinline__ u64 dup2(float x) {
    u64 r;
    asm("mov.b64 %0, {%1, %1};" : "=l"(r) : "r"(__float_as_uint(x)));
    return r;
}
__device__ __forceinline__ u64 fma2(u64 a, u64 b, u64 c) {
    u64 d;
    asm("fma.rn.f32x2 %0, %1, %2, %3;" : "=l"(d) : "l"(a), "l"(b), "l"(c));
    return d;
}
__device__ __forceinline__ void unpack2(u64 v, float& lo, float& hi) {
    u32 a, b;
    asm("mov.b64 {%0, %1}, %2;" : "=r"(a), "=r"(b) : "l"(v));
    lo = __uint_as_float(a); hi = __uint_as_float(b);
}

__device__ __forceinline__ float phi_fn(float t) {
    return (t > 0.f) ? (1.f + t) : __expf(t);
}

__device__ __forceinline__ int read_start(const void* p, int t, int mode) {
    if (mode == 0) return ((const unsigned char*)p)[t] != 0;
    if (mode == 1) return ((const int*)p)[t] != 0;
    return ((const float*)p)[t] != 0.f;
}

// ---------------- bf16 pack helpers ----------------
// packs a into LOW half, b into HIGH half
__device__ __forceinline__ u32 pack_bf16x2(float lo, float hi) {
    u32 r;
    asm("cvt.rn.bf16x2.f32 %0, %1, %2;" : "=r"(r) : "f"(hi), "f"(lo));
    return r;
}
__device__ __forceinline__ float bf16lo_f(u32 p) { return __uint_as_float(p << 16); }
__device__ __forceinline__ float bf16hi_f(u32 p) { return __uint_as_float(p & 0xffff0000u); }

__device__ __forceinline__ u32 smem_to_u32(const void* smem_ptr) {
    u32 addr;
    asm("{ .reg .u64 tmp; cvta.to.shared.u64 tmp, %1; cvt.u32.u64 %0, tmp; }"
        : "=r"(addr) : "l"(smem_ptr));
    return addr;
}

__device__ __forceinline__ void ldsm_x4(u32& r0, u32& r1, u32& r2, u32& r3, u32 addr) {
    asm volatile("ldmatrix.sync.aligned.m8n8.x4.shared.b16 {%0,%1,%2,%3}, [%4];"
        : "=r"(r0), "=r"(r1), "=r"(r2), "=r"(r3) : "r"(addr));
}

__device__ __forceinline__ void mma16816(float* d, const u32* a, u32 b0, u32 b1) {
    asm volatile(
        "mma.sync.aligned.m16n8k16.row.col.f32.bf16.bf16.f32 "
        "{%0,%1,%2,%3}, {%4,%5,%6,%7}, {%8,%9}, {%0,%1,%2,%3};"
        : "+f"(d[0]), "+f"(d[1]), "+f"(d[2]), "+f"(d[3])
        : "r"(a[0]), "r"(a[1]), "r"(a[2]), "r"(a[3]), "r"(b0), "r"(b1));
}

// ---------------- start-dtype classifier ----------------
__global__ void detect_kernel(const unsigned char* __restrict__ p) {
    __shared__ int cnt1, cnt3f;
    if (threadIdx.x == 0) { cnt1 = 0; cnt3f = 0; }
    __syncthreads();
    int l1 = 0, l3 = 0;
    for (int idx = threadIdx.x; idx < 4096; idx += 256) {
        unsigned char b = p[idx];
        if ((idx & 3) != 0 && b != 0) l1++;
        if ((idx & 3) == 3 && b == 0x3F) l3++;
    }
    atomicAdd(&cnt1, l1); atomicAdd(&cnt3f, l3);
    __syncthreads();
    if (threadIdx.x == 0) g_startmode = (cnt3f > 0) ? 2 : ((cnt1 > 0) ? 0 : 1);
}

// ---------------- k,q,v projections ----------------
#define KQV_ROWS 128
__global__ void kqv_kernel(const float* __restrict__ xext, int use_x1,
                           const float* __restrict__ Wk, const float* __restrict__ Wq,
                           const float* __restrict__ Wv, const float* __restrict__ bv)
{
    extern __shared__ float sm[];
    float* wt = sm;                  // 256*64
    float* xs = sm + 256*64;         // 128*257
    const float* x = use_x1 ? g_x1 : xext;
    int tid = threadIdx.x;
    int base = blockIdx.x * KQV_ROWS;

    for (int idx = tid; idx < 48*256; idx += 256) {
        int o = idx >> 8, c = idx & 255;
        float w;
        if (o < 16)      w = Wk[o*256 + c];
        else if (o < 32) w = Wq[(o-16)*256 + c];
        else             w = Wv[(o-32)*256 + c];
        int gg = o / 6, mm = o - gg*6;
        wt[c*64 + gg*8 + mm] = w;
    }
    {
        const float* xg = x + (size_t)base * 256;
        for (int idx = tid; idx < KQV_ROWS*64; idx += 256) {
            int r = idx >> 6, c4 = (idx & 63) * 4;
            float4 v = *(const float4*)(xg + r*256 + c4);
            float* d = xs + r*257 + c4;
            d[0] = v.x; d[1] = v.y; d[2] = v.z; d[3] = v.w;
        }
    }
    __syncthreads();

    int r0 = tid & 31;
    int g  = tid >> 5;
    u64 acc[4][3];
    #pragma unroll
    for (int rr = 0; rr < 4; rr++)
        #pragma unroll
        for (int pi = 0; pi < 3; pi++) acc[rr][pi] = 0ull;

    const float* wbase = wt + g*8;
    #pragma unroll 2
    for (int c = 0; c < 256; c++) {
        const float* wr = wbase + c*64;
        u64 w0 = *(const u64*)(wr + 0);
        u64 w1 = *(const u64*)(wr + 2);
        u64 w2 = *(const u64*)(wr + 4);
        #pragma unroll
        for (int rr = 0; rr < 4; rr++) {
            float xv = xs[(r0 + rr*32)*257 + c];
            u64 xd = dup2(xv);
            acc[rr][0] = fma2(xd, w0, acc[rr][0]);
            acc[rr][1] = fma2(xd, w1, acc[rr][1]);
            acc[rr][2] = fma2(xd, w2, acc[rr][2]);
        }
    }

    #pragma unroll
    for (int rr = 0; rr < 4; rr++) {
        int t = base + r0 + rr*32;
        #pragma unroll
        for (int pi = 0; pi < 3; pi++) {
            float lo, hi;
            unpack2(acc[rr][pi], lo, hi);
            #pragma unroll
            for (int h = 0; h < 2; h++) {
                int o = g*6 + pi*2 + h;
                float val = h ? hi : lo;
                if (o < 16)       g_k[t*16 + o]      = phi_fn(val);
                else if (o < 32)  g_q[t*16 + (o-16)] = phi_fn(val);
                else              g_v[t*16 + (o-32)] = val + bv[o-32];
            }
        }
    }
}

// ---------------- pass 1: chunk aggregates ----------------
__global__ void agg_kernel(const void* __restrict__ startp)
{
    __shared__ float ks[CH*16], vs[CH*16], ksums[CH];
    __shared__ int stb[CH];
    int tid = threadIdx.x;
    int c = blockIdx.x;
    int tb = c * CH;
    int mode = g_startmode;
    for (int idx = tid; idx < CH*16; idx += 256) {
        ks[idx] = g_k[tb*16 + idx];
        vs[idx] = g_v[tb*16 + idx];
    }
    for (int idx = tid; idx < CH; idx += 256)
        stb[idx] = read_start(startp, tb + idx, mode);
    __syncthreads();
    for (int t = tid; t < CH; t += 256) {
        float s = 0.f;
        #pragma unroll
        for (int i = 0; i < 16; i++) s += ks[t*16 + i];
        ksums[t] = s;
    }
    __syncthreads();

    int i = tid & 15, j = tid >> 4;
    float S = 0.f, Zs = 0.f; int p = 0;
    for (int t = 0; t < CH; t++) {
        if (stb[t]) { S = 0.f; Zs = 0.f; p = 1; }
        S  += ks[t*16 + i] * vs[t*16 + j];
        Zs += ksums[t];
    }
    g_Sagg[c*256 + tid] = S;
    if (tid == 0) { g_Zagg[c] = Zs; g_pagg[c] = p; }
}

// ---------------- pass 2: chunk-prefix scan (1 CTA, software-pipelined) --------
#define PD 16
__global__ void prefix_kernel(const float* __restrict__ s0, const float* __restrict__ z0)
{
    int tid = threadIdx.x;
    int i = tid & 15, j = tid >> 4;
    float S = s0[i*16 + j];
    float Zs = 0.f;
    #pragma unroll
    for (int l = 0; l < 16; l++) Zs += z0[l];

    float sa[PD], za[PD]; int pp[PD];
    #pragma unroll
    for (int d = 0; d < PD; d++) {
        sa[d] = g_Sagg[d*256 + tid];
        za[d] = g_Zagg[d];
        pp[d] = g_pagg[d];
    }
    for (int c = 0; c < NC; c += PD) {
        #pragma unroll
        for (int d = 0; d < PD; d++) {
            g_Spre[(c+d)*256 + tid] = S;
            if (tid == 0) g_Zpre[c+d] = Zs;
            float s_ = sa[d], z_ = za[d];
            int   p_ = pp[d];
            int n = c + d + PD;
            if (n < NC) {
                sa[d] = g_Sagg[n*256 + tid];
                za[d] = g_Zagg[n];
                pp[d] = g_pagg[n];
            }
            if (p_) { S = 0.f; Zs = 0.f; }
            S += s_; Zs += z_;
        }
    }
}

// ---------------- pass 3: replay + attention output + MLP layer 1 ----------------
__global__ void apply_kernel(const void* __restrict__ startp,
                             const float* __restrict__ Wm1, const float* __restrict__ bm1)
{
    __shared__ float ks[CH*16], qs[CH*16], vs[CH*16], ksums[CH], qsums[CH];
    __shared__ int stb[CH];
    __shared__ float outb[2][16];
    int tid = threadIdx.x;
    int c = blockIdx.x;
    int tb = c * CH;
    int mode = g_startmode;
    for (int idx = tid; idx < CH*16; idx += 256) {
        ks[idx] = g_k[tb*16 + idx];
        qs[idx] = g_q[tb*16 + idx];
        vs[idx] = g_v[tb*16 + idx];
    }
    for (int idx = tid; idx < CH; idx += 256)
        stb[idx] = read_start(startp, tb + idx, mode);
    __syncthreads();
    for (int t = tid; t < CH; t += 256) {
        float sk = 0.f, sq = 0.f;
        #pragma unroll
        for (int i = 0; i < 16; i++) { sk += ks[t*16+i]; sq += qs[t*16+i]; }
        ksums[t] = sk; qsums[t] = sq;
    }
    float wm1r[16];
    #pragma unroll
    for (int l = 0; l < 16; l++) wm1r[l] = Wm1[tid*16 + l];
    float b1 = bm1[tid];
    float S  = g_Spre[c*256 + tid];
    float Zs = g_Zpre[c];
    __syncthreads();

    int i = tid & 15, j = tid >> 4;
    for (int t = 0; t < CH; t++) {
        if (stb[t]) { S = 0.f; Zs = 0.f; }
        S  += ks[t*16 + i] * vs[t*16 + j];
        Zs += ksums[t];
        float pv = S * qs[t*16 + i];
        pv += __shfl_down_sync(0xffffffffu, pv, 8, 16);
        pv += __shfl_down_sync(0xffffffffu, pv, 4, 16);
        pv += __shfl_down_sync(0xffffffffu, pv, 2, 16);
        pv += __shfl_down_sync(0xffffffffu, pv, 1, 16);
        if (i == 0) {
            float denom = fmaxf(Zs * qsums[t], 1e-6f);
            outb[t & 1][j] = pv / denom;
        }
        __syncthreads();
        const float* ob = outb[t & 1];
        float h = b1;
        #pragma unroll
        for (int l = 0; l < 16; l++) h += wm1r[l] * ob[l];
        h = (h > 0.f) ? h : 0.01f * h;
        g_h1[(size_t)(tb + t) * 256 + tid] = h;
    }
}

// ================= HMMA big GEMM (bf16x3 Dekker split, mma.sync) =================
// variant 0: g_h2   = leaky(g_h1 @ W1^T + b1)                      (K=256)
// variant 1: g_ypre = g_h2 @ W1^T + xext @ W2^T + b1 + b2          (K=512)
// variant 2: g_ypre = g_h2 @ W1^T + g_x1 @ W2^T + b1 + b2          (K=512)
//
// SMEM (bytes): each tile 128 rows x 72 bf16 (stride 144B, conflict-free ldmatrix)
#define TSTRIDE 72
#define OFF_AHI   0
#define OFF_ALO   18432
#define OFF_BHI   36864
#define OFF_BLO   55296
#define OFF_BIAS  73728
#define GEMM_SMEM (73728 + 512)

__global__ void __launch_bounds__(256, 2)
gemm_mma_kernel(const float* __restrict__ xext,
                const float* __restrict__ W1, const float* __restrict__ W2,
                const float* __restrict__ b1p, const float* __restrict__ b2p,
                int variant)
{
    extern __shared__ char smc[];
    u32 sbase = smem_to_u32(smc);
    float* bias_sm = (float*)(smc + OFF_BIAS);

    const float* A1 = (variant == 0) ? g_h1 : g_h2;
    const float* A2 = (variant == 2) ? g_x1 : xext;
    float* C        = (variant == 0) ? g_h2 : g_ypre;
    int nchunk      = (variant == 0) ? 4 : 8;

    int tid  = threadIdx.x;
    int wid  = tid >> 5;
    int lane = tid & 31;
    int colbase = blockIdx.x * 128;
    int rowbase = blockIdx.y * 128;

    int warp_m = (wid >> 1) * 32;
    int warp_n = (wid & 1) * 64;

    for (int i = tid; i < 128; i += 256)
        bias_sm[i] = b1p[colbase + i] + ((variant != 0) ? b2p[colbase + i] : 0.f);

    float acc[2][8][4];
    #pragma unroll
    for (int mi = 0; mi < 2; mi++)
        #pragma unroll
        for (int nt = 0; nt < 8; nt++)
            #pragma unroll
            for (int r = 0; r < 4; r++) acc[mi][nt][r] = 0.f;

    // staging indices: 128 rows x 16 float4 per tile, 2048 float4, 8 per thread
    int srow = tid >> 1;                 // two threads per row, covers 128 rows in 1 sweep of 256? no:
    // use idx loop instead

    for (int kc = 0; kc < nchunk; kc++) {
        int koff = (kc & 3) * 64;
        const float* Ap = (kc < 4) ? A1 : A2;
        const float* Wp = (kc < 4) ? W1 : W2;
        __syncthreads();   // ensure previous chunk's compute done before overwrite
        // stage A (rows rowbase..+128) and B=W (rows colbase..+128), 64 k each
        #pragma unroll
        for (int s = 0; s < 8; s++) {
            int idx = tid + s*256;       // 0..2047
            int row = idx >> 4;
            int kq  = (idx & 15) * 4;
            float4 va = *(const float4*)(Ap + (size_t)(rowbase + row)*256 + koff + kq);
            u32 h0 = pack_bf16x2(va.x, va.y);
            u32 h1 = pack_bf16x2(va.z, va.w);
            u32 l0 = pack_bf16x2(va.x - bf16lo_f(h0), va.y - bf16hi_f(h0));
            u32 l1 = pack_bf16x2(va.z - bf16lo_f(h1), va.w - bf16hi_f(h1));
            int off = (row*TSTRIDE + kq) * 2;
            *(u64*)(smc + OFF_AHI + off) = (u64)h0 | ((u64)h1 << 32);
            *(u64*)(smc + OFF_ALO + off) = (u64)l0 | ((u64)l1 << 32);
            float4 vb = *(const float4*)(Wp + (size_t)(colbase + row)*256 + koff + kq);
            u32 g0 = pack_bf16x2(vb.x, vb.y);
            u32 g1 = pack_bf16x2(vb.z, vb.w);
            u32 m0 = pack_bf16x2(vb.x - bf16lo_f(g0), vb.y - bf16hi_f(g0));
            u32 m1 = pack_bf16x2(vb.z - bf16lo_f(g1), vb.w - bf16hi_f(g1));
            *(u64*)(smc + OFF_BHI + off) = (u64)g0 | ((u64)g1 << 32);
            *(u64*)(smc + OFF_BLO + off) = (u64)m0 | ((u64)m1 << 32);
        }
        __syncthreads();

        // compute: 4 k16 steps
        #pragma unroll
        for (int ks = 0; ks < 4; ks++) {
            int k0 = ks * 16;
            int lrow = lane & 15;
            int lcol = (lane >> 4) * 16;   // byte offset of k8 half
            u32 ahi[2][4], alo[2][4];
            #pragma unroll
            for (int mi = 0; mi < 2; mi++) {
                u32 aoff = (u32)(((warp_m + mi*16 + lrow)*TSTRIDE + k0) * 2) + lcol;
                ldsm_x4(ahi[mi][0], ahi[mi][1], ahi[mi][2], ahi[mi][3], sbase + OFF_AHI + aoff);
                ldsm_x4(alo[mi][0], alo[mi][1], alo[mi][2], alo[mi][3], sbase + OFF_ALO + aoff);
            }
            #pragma unroll
            for (int gg = 0; gg < 4; gg++) {
                u32 boff = (u32)(((warp_n + gg*16 + lrow)*TSTRIDE + k0) * 2) + lcol;
                u32 bh[4], bl[4];
                ldsm_x4(bh[0], bh[1], bh[2], bh[3], sbase + OFF_BHI + boff);
                ldsm_x4(bl[0], bl[1], bl[2], bl[3], sbase + OFF_BLO + boff);
                #pragma unroll
                for (int mi = 0; mi < 2; mi++) {
                    #pragma unroll
                    for (int nj = 0; nj < 2; nj++) {
                        float* d = acc[mi][gg*2 + nj];
                        mma16816(d, ahi[mi], bh[nj], bh[2 + nj]);
                        mma16816(d, ahi[mi], bl[nj], bl[2 + nj]);
                        mma16816(d, alo[mi], bh[nj], bh[2 + nj]);
                    }
                }
            }
        }
    }

    // ---------------- epilogue ----------------
    int act = (variant == 0);
    #pragma unroll
    for (int mi = 0; mi < 2; mi++) {
        int row0 = rowbase + warp_m + mi*16 + (lane >> 2);
        #pragma unroll
        for (int nt = 0; nt < 8; nt++) {
            int colL = warp_n + nt*8 + (lane & 3)*2;
            int col  = colbase + colL;
            float b0 = bias_sm[colL], b1 = bias_sm[colL + 1];
            float v0 = acc[mi][nt][0] + b0;
            float v1 = acc[mi][nt][1] + b1;
            float v2 = acc[mi][nt][2] + b0;
            float v3 = acc[mi][nt][3] + b1;
            if (act) {
                v0 = (v0 > 0.f) ? v0 : 0.01f * v0;
                v1 = (v1 > 0.f) ? v1 : 0.01f * v1;
                v2 = (v2 > 0.f) ? v2 : 0.01f * v2;
                v3 = (v3 > 0.f) ? v3 : 0.01f * v3;
            }
            *(float2*)(C + (size_t)row0 * 256 + col)       = make_float2(v0, v1);
            *(float2*)(C + (size_t)(row0 + 8) * 256 + col) = make_float2(v2, v3);
        }
    }
}

// ---------------- LayerNorm + residual ----------------
// mode 0: g_x1 = xext + LN(g_ypre)   (block 0)
// mode 1: outext = LN(g_ypre)        (block 1, final output)
__global__ void ln_kernel(const float* __restrict__ xext, float* __restrict__ outext,
                          const float* __restrict__ lw, const float* __restrict__ lb, int mode)
{
    int tid = threadIdx.x;
    int lane = tid & 31, w = tid >> 5;
    int row = blockIdx.x * 8 + w;
    const float* yp = g_ypre + (size_t)row * 256;
    float vals[8];
    float s = 0.f;
    #pragma unroll
    for (int u = 0; u < 8; u++) { vals[u] = yp[lane + u*32]; s += vals[u]; }
    #pragma unroll
    for (int d = 16; d >= 1; d >>= 1) s += __shfl_xor_sync(0xffffffffu, s, d);
    float mean = s * (1.f / 256.f);
    float v2 = 0.f;
    #pragma unroll
    for (int u = 0; u < 8; u++) { float d = vals[u] - mean; v2 += d * d; }
    #pragma unroll
    for (int d = 16; d >= 1; d >>= 1) v2 += __shfl_xor_sync(0xffffffffu, v2, d);
    float rstd = rsqrtf(v2 * (1.f / 256.f) + 1e-5f);

    if (mode == 0) {
        float* o = g_x1 + (size_t)row * 256;
        const float* xr = xext + (size_t)row * 256;
        #pragma unroll
        for (int u = 0; u < 8; u++) {
            int cl = lane + u*32;
            o[cl] = xr[cl] + (vals[u] - mean) * rstd * lw[cl] + lb[cl];
        }
    } else {
        float* o = outext + (size_t)row * 256;
        #pragma unroll
        for (int u = 0; u < 8; u++) {
            int cl = lane + u*32;
            o[cl] = (vals[u] - mean) * rstd * lw[cl] + lb[cl];
        }
    }
}

// ---------------- launch ----------------
extern "C" void kernel_launch(void* const* d_in, const int* in_sizes, int n_in,
                              void* d_out, int out_size)
{
    const float* x     = (const float*)d_in[0];
    const void*  start = d_in[1];
    const float* s0    = (const float*)d_in[2];
    const float* z0    = (const float*)d_in[3];
    const float* Wk    = (const float*)d_in[4];
    const float* Wq    = (const float*)d_in[5];
    const float* Wv    = (const float*)d_in[6];
    const float* bv    = (const float*)d_in[7];
    const float* Wskip = (const float*)d_in[8];
    const float* bskip = (const float*)d_in[9];
    const float* Wm1   = (const float*)d_in[10];
    const float* bm1   = (const float*)d_in[11];
    const float* Wm2   = (const float*)d_in[12];
    const float* bm2   = (const float*)d_in[13];
    const float* Wm3   = (const float*)d_in[14];
    const float* bm3   = (const float*)d_in[15];
    const float* lnw   = (const float*)d_in[16];
    const float* lnb   = (const float*)d_in[17];
    float* out = (float*)d_out;

    const int kqv_smem = (256*64 + KQV_ROWS*257) * 4;
    cudaFuncSetAttribute(kqv_kernel, cudaFuncAttributeMaxDynamicSharedMemorySize, kqv_smem);
    cudaFuncSetAttribute(gemm_mma_kernel, cudaFuncAttributeMaxDynamicSharedMemorySize, GEMM_SMEM);

    detect_kernel<<<1, 256>>>((const unsigned char*)start);

    for (int b = 0; b < NBLK; b++) {
        kqv_kernel<<<TT/KQV_ROWS, 256, kqv_smem>>>(x, b,
            Wk + b*16*256, Wq + b*16*256, Wv + b*16*256, bv + b*16);
        agg_kernel<<<NC, 256>>>(start);
        prefix_kernel<<<1, 256>>>(s0 + b*256, z0 + b*16);
        apply_kernel<<<NC, 256>>>(start, Wm1 + b*256*16, bm1 + b*256);
        // h2 = leaky(h1 @ Wm2^T + bm2)
        gemm_mma_kernel<<<dim3(2, TT/128), 256, GEMM_SMEM>>>(x,
            Wm2 + b*256*256, Wm2 + b*256*256, bm2 + b*256, bm2 + b*256, 0);
        // ypre = h2 @ Wm3^T + A2 @ Wskip^T + bm3 + bskip
        gemm_mma_kernel<<<dim3(2, TT/128), 256, GEMM_SMEM>>>(x,
            Wm3 + b*256*256, Wskip + b*256*256, bm3 + b*256, bskip + b*256,
            (b == 0) ? 1 : 2);
        ln_kernel<<<TT/8, 256>>>(x, out, lnw + b*256, lnb + b*256, (b == 0) ? 0 : 1);
    }
}